// round 14
// baseline (speedup 1.0000x reference)
#include <cuda_runtime.h>

#define B_ 2
#define T_ 2048
#define H_ 16
#define DH_ 64
#define DIN_ 1024
#define DINNER_ 1024
#define DOUT_ 64
#define BT_ 4096

#define FULLM 0xffffffffu

// All fp16 operands stored as packed half2 in unsigned words.
__device__ unsigned g_x16[BT_*DIN_/2];        // [row][k2]      half2(k, k+1)
__device__ unsigned g_w16[3][DIN_/2*DINNER_]; // [k2][n]        half2(k, k+1)
__device__ unsigned g_wo16[DINNER_/2*DOUT_];  // [k2][n]        half2(k, k+1)
__device__ unsigned g_Q16[B_*H_*T_*DH_/2];    // [bh][t][d2]    half2(d, d+1)
__device__ unsigned g_K16[B_*H_*T_*DH_/2];    // [bh][t][d2]    half2(d, d+1)
__device__ unsigned g_V16[B_*H_*T_*DH_/2];    // [bh][d][t2]    half2(t, t+1)
__device__ unsigned g_attn16[BT_*DINNER_/2];  // [row][d2]      half2(d, d+1)

__device__ __forceinline__ unsigned packh2(float hi, float lo) {
    unsigned u;
    asm("cvt.rn.f16x2.f32 %0, %1, %2;" : "=r"(u) : "f"(hi), "f"(lo));
    return u;
}
__device__ __forceinline__ void mma16(float c[4],
    unsigned a0, unsigned a1, unsigned a2, unsigned a3,
    unsigned b0, unsigned b1)
{
    asm volatile("mma.sync.aligned.m16n8k16.row.col.f32.f16.f16.f32 "
        "{%0,%1,%2,%3}, {%4,%5,%6,%7}, {%8,%9}, {%0,%1,%2,%3};"
        : "+f"(c[0]), "+f"(c[1]), "+f"(c[2]), "+f"(c[3])
        : "r"(a0), "r"(a1), "r"(a2), "r"(a3), "r"(b0), "r"(b1));
}
__device__ __forceinline__ void ldsm4(unsigned& r0, unsigned& r1,
                                      unsigned& r2, unsigned& r3, unsigned a)
{
    asm volatile("ldmatrix.sync.aligned.m8n8.x4.shared.b16 {%0,%1,%2,%3}, [%4];"
        : "=r"(r0), "=r"(r1), "=r"(r2), "=r"(r3) : "r"(a));
}

// ---------------------------------------------------------------------------
// Kernel 0: pack all GEMM inputs to fp16 half2 in ONE launch.
// ---------------------------------------------------------------------------
#define XU  (BT_*DIN_/4)
#define WU  (DIN_/2*DINNER_)
#define WOU (DINNER_/2*DOUT_)
#define PRETOT (XU + 3*WU + WOU)

__global__ __launch_bounds__(256) void pack16_all(
    const float4* __restrict__ x, const float* __restrict__ wq,
    const float* __restrict__ wk, const float* __restrict__ wv,
    const float* __restrict__ wo)
{
    int i = blockIdx.x * 256 + threadIdx.x;
    if (i >= PRETOT) return;
    if (i < XU) {
        float4 v = x[i];
        g_x16[2 * i]     = packh2(v.y, v.x);
        g_x16[2 * i + 1] = packh2(v.w, v.z);
    } else {
        int j = i - XU;
        if (j < 3 * WU) {
            int w = j >> 19;
            int o = j & (WU - 1);
            int k2 = o >> 10, n = o & 1023;
            const float* W = (w == 0) ? wq : (w == 1) ? wk : wv;
            g_w16[w][o] = packh2(W[(2 * k2 + 1) * DINNER_ + n],
                                 W[(2 * k2) * DINNER_ + n]);
        } else {
            int o = j - 3 * WU;
            int k2 = o >> 6, n = o & 63;
            g_wo16[o] = packh2(wo[(2 * k2 + 1) * DOUT_ + n],
                               wo[(2 * k2) * DOUT_ + n]);
        }
    }
}

// ---------------------------------------------------------------------------
// Kernel 1: fused QKV projection, fp16 mma, cp.async double-buffer.
// NEW: CTA tile 128m x 256n, 256 threads, 8 warps (warp tile 64x64 kept).
// Halves x L2 re-reads (8->4 n-tiles) and wave count (768->384 CTAs).
// A smem [row][k2] stride 20; B smem [k2][n] stride 264 (banks g+8tq: free).
// Epilogue: Q and K [t][d2]; V [d][t2]. Bit-identical accumulation order.
// ---------------------------------------------------------------------------
#define AST 20
#define BST 264
#define ASTG (128*AST)    // 2560 uint
#define BSTG (16*BST)     // 4224 uint
#define QKV_SMEM ((2*ASTG + 2*BSTG)*4)   // 54272 bytes

__global__ __launch_bounds__(256) void qkv_mma_kernel()
{
    extern __shared__ unsigned dsm1[];
    unsigned* As = dsm1;
    unsigned* Bs = dsm1 + 2 * ASTG;

    const int z = blockIdx.z;
    const unsigned* __restrict__ X = g_x16;
    const unsigned* __restrict__ W = g_w16[z];

    const int m0 = blockIdx.y * 128, n0 = blockIdx.x * 256;
    const int tid = threadIdx.x, lane = tid & 31, warp = tid >> 5;
    const int g = lane >> 2, tq = lane & 3;
    const int wm = (warp & 1) * 64, wn = (warp >> 1) * 64;

    const unsigned sA = (unsigned)__cvta_generic_to_shared(As);
    const unsigned sB = (unsigned)__cvta_generic_to_shared(Bs);

#define ISSUE(CH, ST) do {                                                    \
    _Pragma("unroll")                                                         \
    for (int u_ = 0; u_ < 2; u_++) {                                          \
        int i_ = tid + 256 * u_;                                              \
        int row_ = i_ >> 2, c4_ = i_ & 3;                                     \
        const unsigned* ga_ = X + (size_t)(m0 + row_) * (DIN_/2)              \
                              + (CH) * 16 + c4_ * 4;                          \
        unsigned da_ = sA + (unsigned)(((ST) * ASTG + row_ * AST + c4_ * 4) * 4); \
        asm volatile("cp.async.cg.shared.global [%0], [%1], 16;"              \
            :: "r"(da_), "l"(ga_));                                           \
    }                                                                         \
    _Pragma("unroll")                                                         \
    for (int u_ = 0; u_ < 4; u_++) {                                          \
        int j_ = tid + 256 * u_;                                              \
        int kr_ = j_ >> 6, c4_ = j_ & 63;                                     \
        const unsigned* gb_ = W + (size_t)((CH) * 16 + kr_) * DINNER_         \
                              + n0 + c4_ * 4;                                 \
        unsigned db_ = sB + (unsigned)(((ST) * BSTG + kr_ * BST + c4_ * 4) * 4); \
        asm volatile("cp.async.cg.shared.global [%0], [%1], 16;"              \
            :: "r"(db_), "l"(gb_));                                           \
    }                                                                         \
    asm volatile("cp.async.commit_group;" ::: "memory");                      \
} while (0)

    float acc[4][8][4];
    #pragma unroll
    for (int i = 0; i < 4; i++)
        #pragma unroll
        for (int j = 0; j < 8; j++)
            #pragma unroll
            for (int r = 0; r < 4; r++) acc[i][j][r] = 0.f;

    ISSUE(0, 0);

    for (int ch = 0; ch < 32; ++ch) {
        const int st = ch & 1;
        if (ch < 31) {
            ISSUE(ch + 1, st ^ 1);
            asm volatile("cp.async.wait_group 1;" ::: "memory");
        } else {
            asm volatile("cp.async.wait_group 0;" ::: "memory");
        }
        __syncthreads();

        const unsigned* A0 = As + st * ASTG;
        const unsigned* B0 = Bs + st * BSTG;
        #pragma unroll
        for (int ks = 0; ks < 2; ++ks) {
            unsigned a0[4], a1[4], a2[4], a3[4];
            #pragma unroll
            for (int mf = 0; mf < 4; mf++) {
                int r0 = (wm + mf * 16 + g) * AST + ks * 8 + tq;
                int r1 = r0 + 8 * AST;
                a0[mf] = A0[r0];
                a2[mf] = A0[r0 + 4];
                a1[mf] = A0[r1];
                a3[mf] = A0[r1 + 4];
            }
            unsigned b0[8], b1[8];
            #pragma unroll
            for (int nf = 0; nf < 8; nf++) {
                int cidx = wn + nf * 8 + g;
                b0[nf] = B0[(ks * 8 + tq) * BST + cidx];
                b1[nf] = B0[(ks * 8 + tq + 4) * BST + cidx];
            }
            #pragma unroll
            for (int mf = 0; mf < 4; mf++)
                #pragma unroll
                for (int nf = 0; nf < 8; nf++)
                    mma16(acc[mf][nf], a0[mf], a1[mf], a2[mf], a3[mf],
                          b0[nf], b1[nf]);
        }
        __syncthreads();
    }

    // Epilogue
    const int bb = m0 >> 11;
    #pragma unroll
    for (int mf = 0; mf < 4; mf++) {
        int row_a = m0 + wm + mf * 16 + g;
        int row_b = row_a + 8;
        int ta = row_a & 2047, tb = row_b & 2047;
        #pragma unroll
        for (int nf = 0; nf < 8; nf++) {
            int col = n0 + wn + nf * 8 + 2 * tq;
            int h = col >> 6, d = col & 63;     // d even
            float v0 = acc[mf][nf][0], v1 = acc[mf][nf][1];
            float v2 = acc[mf][nf][2], v3 = acc[mf][nf][3];
            if (z == 0) {
                g_Q16[((size_t)((bb * H_ + h) * T_) + ta) * 32 + (d >> 1)]
                    = packh2(v1, v0);
                g_Q16[((size_t)((bb * H_ + h) * T_) + tb) * 32 + (d >> 1)]
                    = packh2(v3, v2);
            } else if (z == 1) {
                g_K16[((size_t)((bb * H_ + h) * T_) + ta) * 32 + (d >> 1)]
                    = packh2(v1, v0);
                g_K16[((size_t)((bb * H_ + h) * T_) + tb) * 32 + (d >> 1)]
                    = packh2(v3, v2);
            } else {
                // V [d][t2]: partner fragment row is lane^4 (rows t, t+1).
                float s0 = __shfl_xor_sync(FULLM, v0, 4);
                float s1 = __shfl_xor_sync(FULLM, v1, 4);
                float s2 = __shfl_xor_sync(FULLM, v2, 4);
                float s3 = __shfl_xor_sync(FULLM, v3, 4);
                bool odd = (g & 1);
                unsigned ua = odd ? packh2(v1, s1) : packh2(s0, v0);
                unsigned ub = odd ? packh2(v3, s3) : packh2(s2, v2);
                int dcol = d + (g & 1);
                g_V16[((size_t)((bb * H_ + h) * DH_) + dcol) * 1024 + (ta >> 1)] = ua;
                g_V16[((size_t)((bb * H_ + h) * DH_) + dcol) * 1024 + (tb >> 1)] = ub;
            }
        }
    }
#undef ISSUE
}

// ---------------------------------------------------------------------------
// Kernel 2: causal flash attention, fp16 mma + ldmatrix (unchanged R13).
// ---------------------------------------------------------------------------
#define TST 36
#define TSTG (64*TST)

__global__ __launch_bounds__(128) void attn_mma_kernel()
{
    __shared__ unsigned Ks[2 * TSTG];
    __shared__ unsigned Vs[2 * TSTG];

    const int qt = 15 - blockIdx.x;       // heavy tiles first
    const int bh = blockIdx.y;
    const int tid = threadIdx.x, warp = tid >> 5, lane = tid & 31;
    const int g = lane >> 2, tq = lane & 3;
    const int q0w = qt * 128 + warp * 32;

    const unsigned* __restrict__ Qp = g_Q16 + (size_t)bh * T_ * 32;
    const unsigned* __restrict__ Kb = g_K16 + (size_t)bh * T_ * 32;   // [t][d2]
    const unsigned* __restrict__ Vb = g_V16 + (size_t)bh * DH_ * 1024;// [d][t2]

    const unsigned sK = (unsigned)__cvta_generic_to_shared(Ks);
    const unsigned sV = (unsigned)__cvta_generic_to_shared(Vs);

    const int lmat = lane >> 3, lrow = lane & 7;
    const unsigned lmBase =
        (unsigned)((((lmat >> 1) * 8 + lrow) * TST + (lmat & 1) * 4) * 4);

#define KV_ISSUE(KT, ST) do {                                                 \
    _Pragma("unroll")                                                         \
    for (int u_ = 0; u_ < 4; u_++) {                                          \
        int f4_ = tid + 128 * u_;                                             \
        int row_ = f4_ >> 3, c_ = f4_ & 7;                                    \
        unsigned dk_ = sK + (unsigned)(((ST) * TSTG + row_ * TST + c_ * 4) * 4); \
        asm volatile("cp.async.cg.shared.global [%0], [%1], 16;"              \
            :: "r"(dk_), "l"(Kb + (size_t)((KT) * 64 + row_) * 32 + c_ * 4)); \
        unsigned dv_ = sV + (unsigned)(((ST) * TSTG + row_ * TST + c_ * 4) * 4); \
        asm volatile("cp.async.cg.shared.global [%0], [%1], 16;"              \
            :: "r"(dv_), "l"(Vb + (size_t)row_ * 1024 + (KT) * 32 + c_ * 4)); \
    }                                                                         \
    asm volatile("cp.async.commit_group;" ::: "memory");                      \
} while (0)

    unsigned qf[2][4][4];
    #pragma unroll
    for (int m = 0; m < 2; m++) {
        const unsigned* qa = Qp + (size_t)(q0w + 16 * m + g) * 32;
        const unsigned* qb = qa + 8 * 32;
        #pragma unroll
        for (int ks = 0; ks < 4; ks++) {
            qf[m][ks][0] = qa[ks * 8 + tq];
            qf[m][ks][1] = qb[ks * 8 + tq];
            qf[m][ks][2] = qa[ks * 8 + tq + 4];
            qf[m][ks][3] = qb[ks * 8 + tq + 4];
        }
    }

    float of[2][8][4];
    #pragma unroll
    for (int m = 0; m < 2; m++)
        #pragma unroll
        for (int d = 0; d < 8; d++)
            #pragma unroll
            for (int r = 0; r < 4; r++) of[m][d][r] = 0.f;
    float ls[2][2] = {{0.f, 0.f}, {0.f, 0.f}};

    const int ktmax = 2 * qt + 1;
    KV_ISSUE(0, 0);

    for (int kt = 0; kt <= ktmax; ++kt) {
        const int st = kt & 1;
        __syncthreads();
        if (kt < ktmax) {
            KV_ISSUE(kt + 1, st ^ 1);
            asm volatile("cp.async.wait_group 1;" ::: "memory");
        } else {
            asm volatile("cp.async.wait_group 0;" ::: "memory");
        }
        __syncthreads();

        if (kt == ktmax && warp < 2) continue;

        const unsigned kbase = sK + (unsigned)(st * TSTG * 4) + lmBase;
        const unsigned vbase = sV + (unsigned)(st * TSTG * 4) + lmBase;

        float c[2][8][4];
        #pragma unroll
        for (int m = 0; m < 2; m++)
            #pragma unroll
            for (int nf = 0; nf < 8; nf++)
                #pragma unroll
                for (int r = 0; r < 4; r++) c[m][nf][r] = 0.f;

        #pragma unroll
        for (int ks = 0; ks < 4; ks++) {
            unsigned b0[8], b1[8];
            #pragma unroll
            for (int nfp = 0; nfp < 4; nfp++) {
                unsigned a = kbase + (unsigned)((nfp * 16 * TST + ks * 8) * 4);
                ldsm4(b0[2 * nfp], b1[2 * nfp],
                      b0[2 * nfp + 1], b1[2 * nfp + 1], a);
            }
            #pragma unroll
            for (int m = 0; m < 2; m++)
                #pragma unroll
                for (int nf = 0; nf < 8; nf++)
                    mma16(c[m][nf], qf[m][ks][0], qf[m][ks][1],
                          qf[m][ks][2], qf[m][ks][3], b0[nf], b1[nf]);
        }

        if (kt >= 2 * qt) {
            const int base = kt * 64;
            #pragma unroll
            for (int m = 0; m < 2; m++) {
                int r0 = q0w + 16 * m + g, r1 = r0 + 8;
                #pragma unroll
                for (int nf = 0; nf < 8; nf++) {
                    int col = base + nf * 8 + 2 * tq;
                    if (col     > r0) c[m][nf][0] = -1e30f;
                    if (col + 1 > r0) c[m][nf][1] = -1e30f;
                    if (col     > r1) c[m][nf][2] = -1e30f;
                    if (col + 1 > r1) c[m][nf][3] = -1e30f;
                }
            }
        }

        #pragma unroll
        for (int m = 0; m < 2; m++)
            #pragma unroll
            for (int nf = 0; nf < 8; nf++) {
                c[m][nf][0] = __expf(c[m][nf][0] * 0.03125f);
                c[m][nf][1] = __expf(c[m][nf][1] * 0.03125f);
                c[m][nf][2] = __expf(c[m][nf][2] * 0.03125f);
                c[m][nf][3] = __expf(c[m][nf][3] * 0.03125f);
                ls[m][0] += c[m][nf][0] + c[m][nf][1];
                ls[m][1] += c[m][nf][2] + c[m][nf][3];
            }

        #pragma unroll
        for (int j = 0; j < 4; j++) {
            unsigned A[2][4];
            #pragma unroll
            for (int m = 0; m < 2; m++) {
                A[m][0] = packh2(c[m][2 * j][1],     c[m][2 * j][0]);
                A[m][1] = packh2(c[m][2 * j][3],     c[m][2 * j][2]);
                A[m][2] = packh2(c[m][2 * j + 1][1], c[m][2 * j + 1][0]);
                A[m][3] = packh2(c[m][2 * j + 1][3], c[m][2 * j + 1][2]);
            }
            unsigned vb0[8], vb1[8];
            #pragma unroll
            for (int dfp = 0; dfp < 4; dfp++) {
                unsigned a = vbase + (unsigned)((dfp * 16 * TST + j * 8) * 4);
                ldsm4(vb0[2 * dfp], vb1[2 * dfp],
                      vb0[2 * dfp + 1], vb1[2 * dfp + 1], a);
            }
            #pragma unroll
            for (int df = 0; df < 8; df++) {
                mma16(of[0][df], A[0][0], A[0][1], A[0][2], A[0][3],
                      vb0[df], vb1[df]);
                mma16(of[1][df], A[1][0], A[1][1], A[1][2], A[1][3],
                      vb0[df], vb1[df]);
            }
        }
    }
#undef KV_ISSUE

    #pragma unroll
    for (int m = 0; m < 2; m++)
        #pragma unroll
        for (int r = 0; r < 2; r++) {
            ls[m][r] += __shfl_xor_sync(FULLM, ls[m][r], 1);
            ls[m][r] += __shfl_xor_sync(FULLM, ls[m][r], 2);
        }

    const int bb = bh >> 4, hh = bh & 15;
    #pragma unroll
    for (int m = 0; m < 2; m++) {
        float i0 = 1.f / ls[m][0], i1 = 1.f / ls[m][1];
        int rowa = q0w + 16 * m + g, rowb = rowa + 8;
        unsigned* oa = g_attn16 + (size_t)(bb * T_ + rowa) * 512 + hh * 32;
        unsigned* ob = g_attn16 + (size_t)(bb * T_ + rowb) * 512 + hh * 32;
        #pragma unroll
        for (int df = 0; df < 8; df++) {
            oa[df * 4 + tq] = packh2(of[m][df][1] * i0, of[m][df][0] * i0);
            ob[df * 4 + tq] = packh2(of[m][df][3] * i1, of[m][df][2] * i1);
        }
    }
}

// ---------------------------------------------------------------------------
// Kernel 3: out projection via fp16 mma (unchanged R10 champion).
// ---------------------------------------------------------------------------
#define OAST 20
#define OBST 72
#define OASTG (32*OAST)
#define OBSTG (16*OBST)

__global__ __launch_bounds__(128) void out_mma_kernel(
    const float* __restrict__ bo, float* __restrict__ out)
{
    __shared__ unsigned As3[2 * OASTG];
    __shared__ unsigned Bs3[2 * OBSTG];

    const int m0 = blockIdx.x * 32;
    const int tid = threadIdx.x, lane = tid & 31, warp = tid >> 5;
    const int g = lane >> 2, tq = lane & 3;
    const int wm = (warp >> 1) * 16, wn = (warp & 1) * 32;

    const unsigned sA = (unsigned)__cvta_generic_to_shared(As3);
    const unsigned sB = (unsigned)__cvta_generic_to_shared(Bs3);

#define OISSUE(CH, ST) do {                                                   \
    {                                                                         \
        int row_ = tid >> 2, c4_ = tid & 3;                                   \
        unsigned da_ = sA + (unsigned)(((ST) * OASTG + row_ * OAST + c4_ * 4) * 4); \
        asm volatile("cp.async.cg.shared.global [%0], [%1], 16;"              \
            :: "r"(da_), "l"(g_attn16 + (size_t)(m0 + row_) * 512             \
                             + (CH) * 16 + c4_ * 4));                         \
    }                                                                         \
    _Pragma("unroll")                                                         \
    for (int u_ = 0; u_ < 2; u_++) {                                          \
        int k2r_ = (tid >> 4) + 8 * u_;                                       \
        int c4_ = tid & 15;                                                   \
        unsigned db_ = sB + (unsigned)(((ST) * OBSTG + k2r_ * OBST + c4_ * 4) * 4); \
        asm volatile("cp.async.cg.shared.global [%0], [%1], 16;"              \
            :: "r"(db_), "l"(g_wo16 + (size_t)((CH) * 16 + k2r_) * 64 + c4_ * 4)); \
    }                                                                         \
    asm volatile("cp.async.commit_group;" ::: "memory");                      \
} while (0)

    float acc[4][4];
    #pragma unroll
    for (int j = 0; j < 4; j++)
        #pragma unroll
        for (int r = 0; r < 4; r++) acc[j][r] = 0.f;

    OISSUE(0, 0);

    for (int ch = 0; ch < 32; ++ch) {
        const int st = ch & 1;
        if (ch < 31) {
            OISSUE(ch + 1, st ^ 1);
            asm volatile("cp.async.wait_group 1;" ::: "memory");
        } else {
            asm volatile("cp.async.wait_group 0;" ::: "memory");
        }
        __syncthreads();

        const unsigned* A0 = As3 + st * OASTG;
        const unsigned* B0 = Bs3 + st * OBSTG;
        #pragma unroll
        for (int ks = 0; ks < 2; ++ks) {
            int r0 = (wm + g) * OAST + ks * 8 + tq;
            int r1 = r0 + 8 * OAST;
            unsigned a0 = A0[r0];
            unsigned a2 = A0[r0 + 4];
            unsigned a1 = A0[r1];
            unsigned a3 = A0[r1 + 4];
            #pragma unroll
            for (int nf = 0; nf < 4; nf++) {
                int cidx = wn + nf * 8 + g;
                unsigned b0 = B0[(ks * 8 + tq) * OBST + cidx];
                unsigned b1 = B0[(ks * 8 + tq + 4) * OBST + cidx];
                mma16(acc[nf], a0, a1, a2, a3, b0, b1);
            }
        }
        __syncthreads();
    }

    const int row_a = m0 + wm + g, row_b = row_a + 8;
    #pragma unroll
    for (int nf = 0; nf < 4; nf++) {
        int col = wn + nf * 8 + 2 * tq;
        float2 bias = *(const float2*)(bo + col);
        *(float2*)(out + (size_t)row_a * DOUT_ + col)
            = make_float2(acc[nf][0] + bias.x, acc[nf][1] + bias.y);
        *(float2*)(out + (size_t)row_b * DOUT_ + col)
            = make_float2(acc[nf][2] + bias.x, acc[nf][3] + bias.y);
    }
#undef OISSUE
}

// ---------------------------------------------------------------------------
extern "C" void kernel_launch(void* const* d_in, const int* in_sizes, int n_in,
                              void* d_out, int out_size)
{
    const float* x  = (const float*)d_in[0];
    const float* Wq = (const float*)d_in[1];
    const float* Wk = (const float*)d_in[2];
    const float* Wv = (const float*)d_in[3];
    const float* Wo = (const float*)d_in[4];
    const float* bo = (const float*)d_in[5];
    float* out = (float*)d_out;
    (void)in_sizes; (void)n_in; (void)out_size;

    cudaFuncSetAttribute(qkv_mma_kernel,
                         cudaFuncAttributeMaxDynamicSharedMemorySize, QKV_SMEM);

    pack16_all<<<(PRETOT + 255) / 256, 256>>>(
        (const float4*)x, Wq, Wk, Wv, Wo);

    qkv_mma_kernel<<<dim3(4, 32, 3), 256, QKV_SMEM>>>();
    attn_mma_kernel<<<dim3(16, 32), 128>>>();
    out_mma_kernel<<<BT_ / 32, 128>>>(bo, out);
}

// round 16
// speedup vs baseline: 1.1664x; 1.1664x over previous
#include <cuda_runtime.h>

#define B_ 2
#define T_ 2048
#define H_ 16
#define DH_ 64
#define DIN_ 1024
#define DINNER_ 1024
#define DOUT_ 64
#define BT_ 4096

#define FULLM 0xffffffffu

// All fp16 operands stored as packed half2 in unsigned words.
__device__ unsigned g_x16[BT_*DIN_/2];        // [row][k2]      half2(k, k+1)
__device__ unsigned g_w16[3][DIN_/2*DINNER_]; // [k2][n]        half2(k, k+1)
__device__ unsigned g_wo16[DINNER_/2*DOUT_];  // [k2][n]        half2(k, k+1)
__device__ unsigned g_Q16[B_*H_*T_*DH_/2];    // [bh][t][d2]    half2(d, d+1)
__device__ unsigned g_K16[B_*H_*T_*DH_/2];    // [bh][d2][t]    half2(d, d+1)
__device__ unsigned g_V16[B_*H_*T_*DH_/2];    // [bh][t2][d]    half2(t, t+1)
__device__ unsigned g_attn16[BT_*DINNER_/2];  // [row][d2]      half2(d, d+1)

__device__ __forceinline__ unsigned packh2(float hi, float lo) {
    unsigned u;
    asm("cvt.rn.f16x2.f32 %0, %1, %2;" : "=r"(u) : "f"(hi), "f"(lo));
    return u;
}
__device__ __forceinline__ void mma16(float c[4],
    unsigned a0, unsigned a1, unsigned a2, unsigned a3,
    unsigned b0, unsigned b1)
{
    asm volatile("mma.sync.aligned.m16n8k16.row.col.f32.f16.f16.f32 "
        "{%0,%1,%2,%3}, {%4,%5,%6,%7}, {%8,%9}, {%0,%1,%2,%3};"
        : "+f"(c[0]), "+f"(c[1]), "+f"(c[2]), "+f"(c[3])
        : "r"(a0), "r"(a1), "r"(a2), "r"(a3), "r"(b0), "r"(b1));
}

// ---------------------------------------------------------------------------
// Kernel 0: pack all GEMM inputs to fp16 half2 in ONE launch.
// ---------------------------------------------------------------------------
#define XU  (BT_*DIN_/4)
#define WU  (DIN_/2*DINNER_)
#define WOU (DINNER_/2*DOUT_)
#define PRETOT (XU + 3*WU + WOU)

__global__ __launch_bounds__(256) void pack16_all(
    const float4* __restrict__ x, const float* __restrict__ wq,
    const float* __restrict__ wk, const float* __restrict__ wv,
    const float* __restrict__ wo)
{
    int i = blockIdx.x * 256 + threadIdx.x;
    if (i >= PRETOT) return;
    if (i < XU) {
        float4 v = x[i];
        g_x16[2 * i]     = packh2(v.y, v.x);
        g_x16[2 * i + 1] = packh2(v.w, v.z);
    } else {
        int j = i - XU;
        if (j < 3 * WU) {
            int w = j >> 19;
            int o = j & (WU - 1);
            int k2 = o >> 10, n = o & 1023;
            const float* W = (w == 0) ? wq : (w == 1) ? wk : wv;
            g_w16[w][o] = packh2(W[(2 * k2 + 1) * DINNER_ + n],
                                 W[(2 * k2) * DINNER_ + n]);
        } else {
            int o = j - 3 * WU;
            int k2 = o >> 6, n = o & 63;
            g_wo16[o] = packh2(wo[(2 * k2 + 1) * DOUT_ + n],
                               wo[(2 * k2) * DOUT_ + n]);
        }
    }
}

// ---------------------------------------------------------------------------
// Kernel 1: fused QKV projection, fp16 mma, cp.async double-buffer
// (R10 champion, unchanged).
// ---------------------------------------------------------------------------
#define AST 20
#define BST 136
#define ASTG (128*AST)
#define BSTG (16*BST)

__global__ __launch_bounds__(128) void qkv_mma_kernel()
{
    __shared__ unsigned As[2 * ASTG];
    __shared__ unsigned Bs[2 * BSTG];

    const int z = blockIdx.z;
    const unsigned* __restrict__ X = g_x16;
    const unsigned* __restrict__ W = g_w16[z];

    const int m0 = blockIdx.y * 128, n0 = blockIdx.x * 128;
    const int tid = threadIdx.x, lane = tid & 31, warp = tid >> 5;
    const int g = lane >> 2, tq = lane & 3;
    const int wm = (warp >> 1) * 64, wn = (warp & 1) * 64;

    const unsigned sA = (unsigned)__cvta_generic_to_shared(As);
    const unsigned sB = (unsigned)__cvta_generic_to_shared(Bs);

    const int ar = tid >> 2, ac4 = tid & 3;
    const int bk = tid >> 5, bc4 = tid & 31;

#define ISSUE(CH, ST) do {                                                    \
    _Pragma("unroll")                                                         \
    for (int u_ = 0; u_ < 4; u_++) {                                          \
        const unsigned* ga_ = X + (size_t)(m0 + ar + 32 * u_) * (DIN_/2)      \
                              + (CH) * 16 + ac4 * 4;                          \
        unsigned da_ = sA + (unsigned)(((ST) * ASTG + (ar + 32 * u_) * AST    \
                              + ac4 * 4) * 4);                                \
        asm volatile("cp.async.cg.shared.global [%0], [%1], 16;"              \
            :: "r"(da_), "l"(ga_));                                           \
    }                                                                         \
    _Pragma("unroll")                                                         \
    for (int u_ = 0; u_ < 4; u_++) {                                          \
        const unsigned* gb_ = W + (size_t)((CH) * 16 + bk + 4 * u_) * DINNER_ \
                              + n0 + bc4 * 4;                                 \
        unsigned db_ = sB + (unsigned)(((ST) * BSTG + (bk + 4 * u_) * BST     \
                              + bc4 * 4) * 4);                                \
        asm volatile("cp.async.cg.shared.global [%0], [%1], 16;"              \
            :: "r"(db_), "l"(gb_));                                           \
    }                                                                         \
    asm volatile("cp.async.commit_group;" ::: "memory");                      \
} while (0)

    float acc[4][8][4];
    #pragma unroll
    for (int i = 0; i < 4; i++)
        #pragma unroll
        for (int j = 0; j < 8; j++)
            #pragma unroll
            for (int r = 0; r < 4; r++) acc[i][j][r] = 0.f;

    ISSUE(0, 0);

    for (int ch = 0; ch < 32; ++ch) {
        const int st = ch & 1;
        if (ch < 31) {
            ISSUE(ch + 1, st ^ 1);
            asm volatile("cp.async.wait_group 1;" ::: "memory");
        } else {
            asm volatile("cp.async.wait_group 0;" ::: "memory");
        }
        __syncthreads();

        const unsigned* A0 = As + st * ASTG;
        const unsigned* B0 = Bs + st * BSTG;
        #pragma unroll
        for (int ks = 0; ks < 2; ++ks) {
            unsigned a0[4], a1[4], a2[4], a3[4];
            #pragma unroll
            for (int mf = 0; mf < 4; mf++) {
                int r0 = (wm + mf * 16 + g) * AST + ks * 8 + tq;
                int r1 = r0 + 8 * AST;
                a0[mf] = A0[r0];
                a2[mf] = A0[r0 + 4];
                a1[mf] = A0[r1];
                a3[mf] = A0[r1 + 4];
            }
            unsigned b0[8], b1[8];
            #pragma unroll
            for (int nf = 0; nf < 8; nf++) {
                int cidx = wn + nf * 8 + g;
                b0[nf] = B0[(ks * 8 + tq) * BST + cidx];
                b1[nf] = B0[(ks * 8 + tq + 4) * BST + cidx];
            }
            #pragma unroll
            for (int mf = 0; mf < 4; mf++)
                #pragma unroll
                for (int nf = 0; nf < 8; nf++)
                    mma16(acc[mf][nf], a0[mf], a1[mf], a2[mf], a3[mf],
                          b0[nf], b1[nf]);
        }
        __syncthreads();
    }

    // Epilogue
    const int bb = m0 >> 11;
    #pragma unroll
    for (int mf = 0; mf < 4; mf++) {
        int row_a = m0 + wm + mf * 16 + g;
        int row_b = row_a + 8;
        int ta = row_a & 2047, tb = row_b & 2047;
        #pragma unroll
        for (int nf = 0; nf < 8; nf++) {
            int col = n0 + wn + nf * 8 + 2 * tq;
            int h = col >> 6, d = col & 63;     // d even
            float v0 = acc[mf][nf][0], v1 = acc[mf][nf][1];
            float v2 = acc[mf][nf][2], v3 = acc[mf][nf][3];
            if (z == 0) {
                g_Q16[((size_t)((bb * H_ + h) * T_) + ta) * 32 + (d >> 1)]
                    = packh2(v1, v0);
                g_Q16[((size_t)((bb * H_ + h) * T_) + tb) * 32 + (d >> 1)]
                    = packh2(v3, v2);
            } else if (z == 1) {
                g_K16[((size_t)((bb * H_ + h) * 32) + (d >> 1)) * T_ + ta]
                    = packh2(v1, v0);
                g_K16[((size_t)((bb * H_ + h) * 32) + (d >> 1)) * T_ + tb]
                    = packh2(v3, v2);
            } else {
                // V^T packed along t: partner fragment row is lane^4.
                float s0 = __shfl_xor_sync(FULLM, v0, 4);
                float s1 = __shfl_xor_sync(FULLM, v1, 4);
                float s2 = __shfl_xor_sync(FULLM, v2, 4);
                float s3 = __shfl_xor_sync(FULLM, v3, 4);
                bool odd = (g & 1);
                unsigned ua = odd ? packh2(v1, s1) : packh2(s0, v0);
                unsigned ub = odd ? packh2(v3, s3) : packh2(s2, v2);
                int dcol = d + (g & 1);
                g_V16[((size_t)((bb * H_ + h) * 1024) + (ta >> 1)) * 64 + dcol] = ua;
                g_V16[((size_t)((bb * H_ + h) * 1024) + (tb >> 1)) * 64 + dcol] = ub;
            }
        }
    }
#undef ISSUE
}

// ---------------------------------------------------------------------------
// Kernel 2: causal flash attention, fp16 mma (R10 body). DELTA: 1-D grid of
// 512 blocks with a serpentine heavy/light task permutation so blocks
// {b, b+148, b+296, b+444} (which share an SM) have near-uniform total work.
// Math and per-task output identical to R10 (bit-identical result).
// ---------------------------------------------------------------------------
#define KST 72
#define VST 72
#define KSTG (64*KST)
#define VSTG (64*VST)
#define ATTN_SMEM ((2*KSTG + 2*VSTG)*4)   // 73728 bytes... (static here: 36,864B halves) 

__global__ __launch_bounds__(128) void attn_mma_kernel()
{
    __shared__ unsigned Ks[2 * (32*KST)];
    __shared__ unsigned Vs[2 * (32*VST)];

    // serpentine rank -> (qt, bh)
    const int b = blockIdx.x;
    int rank;
    if (b < 148)      rank = b;
    else if (b < 296) rank = 443 - b;
    else if (b < 444) rank = b;
    else              rank = 955 - b;
    const int qt = 15 - (rank >> 5);
    const int bh = rank & 31;

    const int tid = threadIdx.x, warp = tid >> 5, lane = tid & 31;
    const int g = lane >> 2, tq = lane & 3;
    const int q0w = qt * 128 + warp * 32;

    const unsigned* __restrict__ Qp = g_Q16 + (size_t)bh * T_ * 32;
    const unsigned* __restrict__ Kb = g_K16 + (size_t)bh * 32 * T_;
    const unsigned* __restrict__ Vb = g_V16 + (size_t)bh * 1024 * 64;

    const unsigned sK = (unsigned)__cvta_generic_to_shared(Ks);
    const unsigned sV = (unsigned)__cvta_generic_to_shared(Vs);

#define KSTG2 (32*KST)
#define VSTG2 (32*VST)
#define KV_ISSUE(KT, ST) do {                                                 \
    _Pragma("unroll")                                                         \
    for (int u_ = 0; u_ < 4; u_++) {                                          \
        int row_ = (tid >> 4) + 8 * u_;                                       \
        int c4_ = tid & 15;                                                   \
        unsigned dk_ = sK + (unsigned)(((ST) * KSTG2 + row_ * KST + c4_ * 4) * 4); \
        asm volatile("cp.async.cg.shared.global [%0], [%1], 16;"              \
            :: "r"(dk_), "l"(Kb + (size_t)row_ * T_ + (KT) * 64 + c4_ * 4));  \
        unsigned dv_ = sV + (unsigned)(((ST) * VSTG2 + row_ * VST + c4_ * 4) * 4); \
        asm volatile("cp.async.cg.shared.global [%0], [%1], 16;"              \
            :: "r"(dv_), "l"(Vb + (size_t)((KT) * 32 + row_) * 64 + c4_ * 4)); \
    }                                                                         \
    asm volatile("cp.async.commit_group;" ::: "memory");                      \
} while (0)

    // Q fragments (raw fp16 half2 bits; 1/32 scale folded into expf)
    unsigned qf[2][4][4];
    #pragma unroll
    for (int m = 0; m < 2; m++) {
        const unsigned* qa = Qp + (size_t)(q0w + 16 * m + g) * 32;
        const unsigned* qb = qa + 8 * 32;
        #pragma unroll
        for (int ks = 0; ks < 4; ks++) {
            qf[m][ks][0] = qa[ks * 8 + tq];
            qf[m][ks][1] = qb[ks * 8 + tq];
            qf[m][ks][2] = qa[ks * 8 + tq + 4];
            qf[m][ks][3] = qb[ks * 8 + tq + 4];
        }
    }

    float of[2][8][4];
    #pragma unroll
    for (int m = 0; m < 2; m++)
        #pragma unroll
        for (int d = 0; d < 8; d++)
            #pragma unroll
            for (int r = 0; r < 4; r++) of[m][d][r] = 0.f;
    float ls[2][2] = {{0.f, 0.f}, {0.f, 0.f}};

    const int ktmax = 2 * qt + 1;
    KV_ISSUE(0, 0);

    for (int kt = 0; kt <= ktmax; ++kt) {
        const int st = kt & 1;
        __syncthreads();
        if (kt < ktmax) {
            KV_ISSUE(kt + 1, st ^ 1);
            asm volatile("cp.async.wait_group 1;" ::: "memory");
        } else {
            asm volatile("cp.async.wait_group 0;" ::: "memory");
        }
        __syncthreads();

        // Fully-masked warps skip the last diagonal tile (bit-identical).
        if (kt == ktmax && warp < 2) continue;

        const unsigned* K0 = Ks + st * KSTG2;
        const unsigned* V0 = Vs + st * VSTG2;

        // ---- S = Q K^T ----
        float c[2][8][4];
        #pragma unroll
        for (int m = 0; m < 2; m++)
            #pragma unroll
            for (int nf = 0; nf < 8; nf++)
                #pragma unroll
                for (int r = 0; r < 4; r++) c[m][nf][r] = 0.f;

        #pragma unroll
        for (int ks = 0; ks < 4; ks++) {
            unsigned b0[8], b1[8];
            #pragma unroll
            for (int nf = 0; nf < 8; nf++) {
                int cidx = nf * 8 + g;
                b0[nf] = K0[(ks * 8 + tq) * KST + cidx];
                b1[nf] = K0[(ks * 8 + tq + 4) * KST + cidx];
            }
            #pragma unroll
            for (int m = 0; m < 2; m++)
                #pragma unroll
                for (int nf = 0; nf < 8; nf++)
                    mma16(c[m][nf], qf[m][ks][0], qf[m][ks][1],
                          qf[m][ks][2], qf[m][ks][3], b0[nf], b1[nf]);
        }

        // ---- causal mask ----
        if (kt >= 2 * qt) {
            const int base = kt * 64;
            #pragma unroll
            for (int m = 0; m < 2; m++) {
                int r0 = q0w + 16 * m + g, r1 = r0 + 8;
                #pragma unroll
                for (int nf = 0; nf < 8; nf++) {
                    int col = base + nf * 8 + 2 * tq;
                    if (col     > r0) c[m][nf][0] = -1e30f;
                    if (col + 1 > r0) c[m][nf][1] = -1e30f;
                    if (col     > r1) c[m][nf][2] = -1e30f;
                    if (col + 1 > r1) c[m][nf][3] = -1e30f;
                }
            }
        }

        // ---- p = exp(s/32) ----
        #pragma unroll
        for (int m = 0; m < 2; m++)
            #pragma unroll
            for (int nf = 0; nf < 8; nf++) {
                c[m][nf][0] = __expf(c[m][nf][0] * 0.03125f);
                c[m][nf][1] = __expf(c[m][nf][1] * 0.03125f);
                c[m][nf][2] = __expf(c[m][nf][2] * 0.03125f);
                c[m][nf][3] = __expf(c[m][nf][3] * 0.03125f);
                ls[m][0] += c[m][nf][0] + c[m][nf][1];
                ls[m][1] += c[m][nf][2] + c[m][nf][3];
            }

        // ---- O += P V : pack P directly into A-fragments ----
        #pragma unroll
        for (int j = 0; j < 4; j++) {
            unsigned A[2][4];
            #pragma unroll
            for (int m = 0; m < 2; m++) {
                A[m][0] = packh2(c[m][2 * j][1],     c[m][2 * j][0]);
                A[m][1] = packh2(c[m][2 * j][3],     c[m][2 * j][2]);
                A[m][2] = packh2(c[m][2 * j + 1][1], c[m][2 * j + 1][0]);
                A[m][3] = packh2(c[m][2 * j + 1][3], c[m][2 * j + 1][2]);
            }
            #pragma unroll
            for (int df = 0; df < 8; df++) {
                int cidx = df * 8 + g;
                unsigned vb0 = V0[(j * 8 + tq) * VST + cidx];
                unsigned vb1 = V0[(j * 8 + tq + 4) * VST + cidx];
                mma16(of[0][df], A[0][0], A[0][1], A[0][2], A[0][3], vb0, vb1);
                mma16(of[1][df], A[1][0], A[1][1], A[1][2], A[1][3], vb0, vb1);
            }
        }
    }
#undef KV_ISSUE

    #pragma unroll
    for (int m = 0; m < 2; m++)
        #pragma unroll
        for (int r = 0; r < 2; r++) {
            ls[m][r] += __shfl_xor_sync(FULLM, ls[m][r], 1);
            ls[m][r] += __shfl_xor_sync(FULLM, ls[m][r], 2);
        }

    // epilogue: fp16-pack g_attn (consumed by out-proj mma)
    const int bb = bh >> 4, hh = bh & 15;
    #pragma unroll
    for (int m = 0; m < 2; m++) {
        float i0 = 1.f / ls[m][0], i1 = 1.f / ls[m][1];
        int rowa = q0w + 16 * m + g, rowb = rowa + 8;
        unsigned* oa = g_attn16 + (size_t)(bb * T_ + rowa) * 512 + hh * 32;
        unsigned* ob = g_attn16 + (size_t)(bb * T_ + rowb) * 512 + hh * 32;
        #pragma unroll
        for (int df = 0; df < 8; df++) {
            oa[df * 4 + tq] = packh2(of[m][df][1] * i0, of[m][df][0] * i0);
            ob[df * 4 + tq] = packh2(of[m][df][3] * i1, of[m][df][2] * i1);
        }
    }
}

// ---------------------------------------------------------------------------
// Kernel 3: out projection via fp16 mma. DELTA vs R10: 4-stage cp.async
// ring (was 2) to hide the 32-chunk serial latency chain.
// ---------------------------------------------------------------------------
#define OAST 20
#define OBST 72
#define OASTG (32*OAST)
#define OBSTG (16*OBST)

__global__ __launch_bounds__(128) void out_mma_kernel(
    const float* __restrict__ bo, float* __restrict__ out)
{
    __shared__ unsigned As3[4 * OASTG];
    __shared__ unsigned Bs3[4 * OBSTG];

    const int m0 = blockIdx.x * 32;
    const int tid = threadIdx.x, lane = tid & 31, warp = tid >> 5;
    const int g = lane >> 2, tq = lane & 3;
    const int wm = (warp >> 1) * 16, wn = (warp & 1) * 32;

    const unsigned sA = (unsigned)__cvta_generic_to_shared(As3);
    const unsigned sB = (unsigned)__cvta_generic_to_shared(Bs3);

#define OISSUE(CH, ST) do {                                                   \
    {                                                                         \
        int row_ = tid >> 2, c4_ = tid & 3;                                   \
        unsigned da_ = sA + (unsigned)(((ST) * OASTG + row_ * OAST + c4_ * 4) * 4); \
        asm volatile("cp.async.cg.shared.global [%0], [%1], 16;"              \
            :: "r"(da_), "l"(g_attn16 + (size_t)(m0 + row_) * 512             \
                             + (CH) * 16 + c4_ * 4));                         \
    }                                                                         \
    _Pragma("unroll")                                                         \
    for (int u_ = 0; u_ < 2; u_++) {                                          \
        int k2r_ = (tid >> 4) + 8 * u_;                                       \
        int c4_ = tid & 15;                                                   \
        unsigned db_ = sB + (unsigned)(((ST) * OBSTG + k2r_ * OBST + c4_ * 4) * 4); \
        asm volatile("cp.async.cg.shared.global [%0], [%1], 16;"              \
            :: "r"(db_), "l"(g_wo16 + (size_t)((CH) * 16 + k2r_) * 64 + c4_ * 4)); \
    }                                                                         \
    asm volatile("cp.async.commit_group;" ::: "memory");                      \
} while (0)

    float acc[4][4];
    #pragma unroll
    for (int j = 0; j < 4; j++)
        #pragma unroll
        for (int r = 0; r < 4; r++) acc[j][r] = 0.f;

    OISSUE(0, 0);
    OISSUE(1, 1);
    OISSUE(2, 2);

    for (int ch = 0; ch < 32; ++ch) {
        const int st = ch & 3;
        __syncthreads();   // all warps done with chunk ch-1 (slot (ch+3)&3)
        if (ch < 29) {
            OISSUE(ch + 3, (ch + 3) & 3);
            asm volatile("cp.async.wait_group 3;" ::: "memory");
        } else if (ch == 29) {
            asm volatile("cp.async.wait_group 2;" ::: "memory");
        } else if (ch == 30) {
            asm volatile("cp.async.wait_group 1;" ::: "memory");
        } else {
            asm volatile("cp.async.wait_group 0;" ::: "memory");
        }
        __syncthreads();

        const unsigned* A0 = As3 + st * OASTG;
        const unsigned* B0 = Bs3 + st * OBSTG;
        #pragma unroll
        for (int ks = 0; ks < 2; ++ks) {
            int r0 = (wm + g) * OAST + ks * 8 + tq;
            int r1 = r0 + 8 * OAST;
            unsigned a0 = A0[r0];
            unsigned a2 = A0[r0 + 4];
            unsigned a1 = A0[r1];
            unsigned a3 = A0[r1 + 4];
            #pragma unroll
            for (int nf = 0; nf < 4; nf++) {
                int cidx = wn + nf * 8 + g;
                unsigned b0 = B0[(ks * 8 + tq) * OBST + cidx];
                unsigned b1 = B0[(ks * 8 + tq + 4) * OBST + cidx];
                mma16(acc[nf], a0, a1, a2, a3, b0, b1);
            }
        }
    }

    const int row_a = m0 + wm + g, row_b = row_a + 8;
    #pragma unroll
    for (int nf = 0; nf < 4; nf++) {
        int col = wn + nf * 8 + 2 * tq;
        float2 bias = *(const float2*)(bo + col);
        *(float2*)(out + (size_t)row_a * DOUT_ + col)
            = make_float2(acc[nf][0] + bias.x, acc[nf][1] + bias.y);
        *(float2*)(out + (size_t)row_b * DOUT_ + col)
            = make_float2(acc[nf][2] + bias.x, acc[nf][3] + bias.y);
    }
#undef OISSUE
}

// ---------------------------------------------------------------------------
extern "C" void kernel_launch(void* const* d_in, const int* in_sizes, int n_in,
                              void* d_out, int out_size)
{
    const float* x  = (const float*)d_in[0];
    const float* Wq = (const float*)d_in[1];
    const float* Wk = (const float*)d_in[2];
    const float* Wv = (const float*)d_in[3];
    const float* Wo = (const float*)d_in[4];
    const float* bo = (const float*)d_in[5];
    float* out = (float*)d_out;
    (void)in_sizes; (void)n_in; (void)out_size;

    pack16_all<<<(PRETOT + 255) / 256, 256>>>(
        (const float4*)x, Wq, Wk, Wv, Wo);

    qkv_mma_kernel<<<dim3(8, 32, 3), 128>>>();
    attn_mma_kernel<<<512, 128>>>();
    out_mma_kernel<<<BT_ / 32, 128>>>(bo, out);
}

// round 17
// speedup vs baseline: 1.1714x; 1.0042x over previous
#include <cuda_runtime.h>

#define B_ 2
#define T_ 2048
#define H_ 16
#define DH_ 64
#define DIN_ 1024
#define DINNER_ 1024
#define DOUT_ 64
#define BT_ 4096

#define FULLM 0xffffffffu

// All fp16 operands stored as packed half2 in unsigned words.
__device__ unsigned g_x16[BT_*DIN_/2];        // [row][k2]      half2(k, k+1)
__device__ unsigned g_w16[3][DIN_/2*DINNER_]; // [k2][n]        half2(k, k+1)
__device__ unsigned g_wo16[DINNER_/2*DOUT_];  // [k2][n]        half2(k, k+1)
__device__ unsigned g_Q16[B_*H_*T_*DH_/2];    // [bh][t][d2]    half2(d, d+1)
__device__ unsigned g_K16[B_*H_*T_*DH_/2];    // [bh][d2][t]    half2(d, d+1)
__device__ unsigned g_V16[B_*H_*T_*DH_/2];    // [bh][t2][d]    half2(t, t+1)
__device__ unsigned g_attn16[BT_*DINNER_/2];  // [row][d2]      half2(d, d+1)

__device__ __forceinline__ unsigned packh2(float hi, float lo) {
    unsigned u;
    asm("cvt.rn.f16x2.f32 %0, %1, %2;" : "=r"(u) : "f"(hi), "f"(lo));
    return u;
}
__device__ __forceinline__ void mma16(float c[4],
    unsigned a0, unsigned a1, unsigned a2, unsigned a3,
    unsigned b0, unsigned b1)
{
    asm volatile("mma.sync.aligned.m16n8k16.row.col.f32.f16.f16.f32 "
        "{%0,%1,%2,%3}, {%4,%5,%6,%7}, {%8,%9}, {%0,%1,%2,%3};"
        : "+f"(c[0]), "+f"(c[1]), "+f"(c[2]), "+f"(c[3])
        : "r"(a0), "r"(a1), "r"(a2), "r"(a3), "r"(b0), "r"(b1));
}

// ---------------------------------------------------------------------------
// Kernel 0: pack all GEMM inputs to fp16 half2 in ONE launch.
// ---------------------------------------------------------------------------
#define XU  (BT_*DIN_/4)
#define WU  (DIN_/2*DINNER_)
#define WOU (DINNER_/2*DOUT_)
#define PRETOT (XU + 3*WU + WOU)

__global__ __launch_bounds__(256) void pack16_all(
    const float4* __restrict__ x, const float* __restrict__ wq,
    const float* __restrict__ wk, const float* __restrict__ wv,
    const float* __restrict__ wo)
{
    int i = blockIdx.x * 256 + threadIdx.x;
    if (i >= PRETOT) return;
    if (i < XU) {
        float4 v = x[i];
        g_x16[2 * i]     = packh2(v.y, v.x);
        g_x16[2 * i + 1] = packh2(v.w, v.z);
    } else {
        int j = i - XU;
        if (j < 3 * WU) {
            int w = j >> 19;
            int o = j & (WU - 1);
            int k2 = o >> 10, n = o & 1023;
            const float* W = (w == 0) ? wq : (w == 1) ? wk : wv;
            g_w16[w][o] = packh2(W[(2 * k2 + 1) * DINNER_ + n],
                                 W[(2 * k2) * DINNER_ + n]);
        } else {
            int o = j - 3 * WU;
            int k2 = o >> 6, n = o & 63;
            g_wo16[o] = packh2(wo[(2 * k2 + 1) * DOUT_ + n],
                               wo[(2 * k2) * DOUT_ + n]);
        }
    }
}

// ---------------------------------------------------------------------------
// Kernel 1: fused QKV projection, fp16 mma, cp.async double-buffer
// (R10 champion, unchanged).
// ---------------------------------------------------------------------------
#define AST 20
#define BST 136
#define ASTG (128*AST)
#define BSTG (16*BST)

__global__ __launch_bounds__(128) void qkv_mma_kernel()
{
    __shared__ unsigned As[2 * ASTG];
    __shared__ unsigned Bs[2 * BSTG];

    const int z = blockIdx.z;
    const unsigned* __restrict__ X = g_x16;
    const unsigned* __restrict__ W = g_w16[z];

    const int m0 = blockIdx.y * 128, n0 = blockIdx.x * 128;
    const int tid = threadIdx.x, lane = tid & 31, warp = tid >> 5;
    const int g = lane >> 2, tq = lane & 3;
    const int wm = (warp >> 1) * 64, wn = (warp & 1) * 64;

    const unsigned sA = (unsigned)__cvta_generic_to_shared(As);
    const unsigned sB = (unsigned)__cvta_generic_to_shared(Bs);

    const int ar = tid >> 2, ac4 = tid & 3;
    const int bk = tid >> 5, bc4 = tid & 31;

#define ISSUE(CH, ST) do {                                                    \
    _Pragma("unroll")                                                         \
    for (int u_ = 0; u_ < 4; u_++) {                                          \
        const unsigned* ga_ = X + (size_t)(m0 + ar + 32 * u_) * (DIN_/2)      \
                              + (CH) * 16 + ac4 * 4;                          \
        unsigned da_ = sA + (unsigned)(((ST) * ASTG + (ar + 32 * u_) * AST    \
                              + ac4 * 4) * 4);                                \
        asm volatile("cp.async.cg.shared.global [%0], [%1], 16;"              \
            :: "r"(da_), "l"(ga_));                                           \
    }                                                                         \
    _Pragma("unroll")                                                         \
    for (int u_ = 0; u_ < 4; u_++) {                                          \
        const unsigned* gb_ = W + (size_t)((CH) * 16 + bk + 4 * u_) * DINNER_ \
                              + n0 + bc4 * 4;                                 \
        unsigned db_ = sB + (unsigned)(((ST) * BSTG + (bk + 4 * u_) * BST     \
                              + bc4 * 4) * 4);                                \
        asm volatile("cp.async.cg.shared.global [%0], [%1], 16;"              \
            :: "r"(db_), "l"(gb_));                                           \
    }                                                                         \
    asm volatile("cp.async.commit_group;" ::: "memory");                      \
} while (0)

    float acc[4][8][4];
    #pragma unroll
    for (int i = 0; i < 4; i++)
        #pragma unroll
        for (int j = 0; j < 8; j++)
            #pragma unroll
            for (int r = 0; r < 4; r++) acc[i][j][r] = 0.f;

    ISSUE(0, 0);

    for (int ch = 0; ch < 32; ++ch) {
        const int st = ch & 1;
        if (ch < 31) {
            ISSUE(ch + 1, st ^ 1);
            asm volatile("cp.async.wait_group 1;" ::: "memory");
        } else {
            asm volatile("cp.async.wait_group 0;" ::: "memory");
        }
        __syncthreads();

        const unsigned* A0 = As + st * ASTG;
        const unsigned* B0 = Bs + st * BSTG;
        #pragma unroll
        for (int ks = 0; ks < 2; ++ks) {
            unsigned a0[4], a1[4], a2[4], a3[4];
            #pragma unroll
            for (int mf = 0; mf < 4; mf++) {
                int r0 = (wm + mf * 16 + g) * AST + ks * 8 + tq;
                int r1 = r0 + 8 * AST;
                a0[mf] = A0[r0];
                a2[mf] = A0[r0 + 4];
                a1[mf] = A0[r1];
                a3[mf] = A0[r1 + 4];
            }
            unsigned b0[8], b1[8];
            #pragma unroll
            for (int nf = 0; nf < 8; nf++) {
                int cidx = wn + nf * 8 + g;
                b0[nf] = B0[(ks * 8 + tq) * BST + cidx];
                b1[nf] = B0[(ks * 8 + tq + 4) * BST + cidx];
            }
            #pragma unroll
            for (int mf = 0; mf < 4; mf++)
                #pragma unroll
                for (int nf = 0; nf < 8; nf++)
                    mma16(acc[mf][nf], a0[mf], a1[mf], a2[mf], a3[mf],
                          b0[nf], b1[nf]);
        }
        __syncthreads();
    }

    // Epilogue
    const int bb = m0 >> 11;
    #pragma unroll
    for (int mf = 0; mf < 4; mf++) {
        int row_a = m0 + wm + mf * 16 + g;
        int row_b = row_a + 8;
        int ta = row_a & 2047, tb = row_b & 2047;
        #pragma unroll
        for (int nf = 0; nf < 8; nf++) {
            int col = n0 + wn + nf * 8 + 2 * tq;
            int h = col >> 6, d = col & 63;     // d even
            float v0 = acc[mf][nf][0], v1 = acc[mf][nf][1];
            float v2 = acc[mf][nf][2], v3 = acc[mf][nf][3];
            if (z == 0) {
                g_Q16[((size_t)((bb * H_ + h) * T_) + ta) * 32 + (d >> 1)]
                    = packh2(v1, v0);
                g_Q16[((size_t)((bb * H_ + h) * T_) + tb) * 32 + (d >> 1)]
                    = packh2(v3, v2);
            } else if (z == 1) {
                g_K16[((size_t)((bb * H_ + h) * 32) + (d >> 1)) * T_ + ta]
                    = packh2(v1, v0);
                g_K16[((size_t)((bb * H_ + h) * 32) + (d >> 1)) * T_ + tb]
                    = packh2(v3, v2);
            } else {
                // V^T packed along t: partner fragment row is lane^4.
                float s0 = __shfl_xor_sync(FULLM, v0, 4);
                float s1 = __shfl_xor_sync(FULLM, v1, 4);
                float s2 = __shfl_xor_sync(FULLM, v2, 4);
                float s3 = __shfl_xor_sync(FULLM, v3, 4);
                bool odd = (g & 1);
                unsigned ua = odd ? packh2(v1, s1) : packh2(s0, v0);
                unsigned ub = odd ? packh2(v3, s3) : packh2(s2, v2);
                int dcol = d + (g & 1);
                g_V16[((size_t)((bb * H_ + h) * 1024) + (ta >> 1)) * 64 + dcol] = ua;
                g_V16[((size_t)((bb * H_ + h) * 1024) + (tb >> 1)) * 64 + dcol] = ub;
            }
        }
    }
#undef ISSUE
}

// ---------------------------------------------------------------------------
// Kernel 2: causal flash attention, fp16 mma, serpentine task map
// (R16 winner, unchanged).
// ---------------------------------------------------------------------------
#define KST 72
#define VST 72

__global__ __launch_bounds__(128) void attn_mma_kernel()
{
    __shared__ unsigned Ks[2 * (32*KST)];
    __shared__ unsigned Vs[2 * (32*VST)];

    // serpentine rank -> (qt, bh)
    const int b = blockIdx.x;
    int rank;
    if (b < 148)      rank = b;
    else if (b < 296) rank = 443 - b;
    else if (b < 444) rank = b;
    else              rank = 955 - b;
    const int qt = 15 - (rank >> 5);
    const int bh = rank & 31;

    const int tid = threadIdx.x, warp = tid >> 5, lane = tid & 31;
    const int g = lane >> 2, tq = lane & 3;
    const int q0w = qt * 128 + warp * 32;

    const unsigned* __restrict__ Qp = g_Q16 + (size_t)bh * T_ * 32;
    const unsigned* __restrict__ Kb = g_K16 + (size_t)bh * 32 * T_;
    const unsigned* __restrict__ Vb = g_V16 + (size_t)bh * 1024 * 64;

    const unsigned sK = (unsigned)__cvta_generic_to_shared(Ks);
    const unsigned sV = (unsigned)__cvta_generic_to_shared(Vs);

#define KSTG2 (32*KST)
#define VSTG2 (32*VST)
#define KV_ISSUE(KT, ST) do {                                                 \
    _Pragma("unroll")                                                         \
    for (int u_ = 0; u_ < 4; u_++) {                                          \
        int row_ = (tid >> 4) + 8 * u_;                                       \
        int c4_ = tid & 15;                                                   \
        unsigned dk_ = sK + (unsigned)(((ST) * KSTG2 + row_ * KST + c4_ * 4) * 4); \
        asm volatile("cp.async.cg.shared.global [%0], [%1], 16;"              \
            :: "r"(dk_), "l"(Kb + (size_t)row_ * T_ + (KT) * 64 + c4_ * 4));  \
        unsigned dv_ = sV + (unsigned)(((ST) * VSTG2 + row_ * VST + c4_ * 4) * 4); \
        asm volatile("cp.async.cg.shared.global [%0], [%1], 16;"              \
            :: "r"(dv_), "l"(Vb + (size_t)((KT) * 32 + row_) * 64 + c4_ * 4)); \
    }                                                                         \
    asm volatile("cp.async.commit_group;" ::: "memory");                      \
} while (0)

    // Q fragments (raw fp16 half2 bits; 1/32 scale folded into expf)
    unsigned qf[2][4][4];
    #pragma unroll
    for (int m = 0; m < 2; m++) {
        const unsigned* qa = Qp + (size_t)(q0w + 16 * m + g) * 32;
        const unsigned* qb = qa + 8 * 32;
        #pragma unroll
        for (int ks = 0; ks < 4; ks++) {
            qf[m][ks][0] = qa[ks * 8 + tq];
            qf[m][ks][1] = qb[ks * 8 + tq];
            qf[m][ks][2] = qa[ks * 8 + tq + 4];
            qf[m][ks][3] = qb[ks * 8 + tq + 4];
        }
    }

    float of[2][8][4];
    #pragma unroll
    for (int m = 0; m < 2; m++)
        #pragma unroll
        for (int d = 0; d < 8; d++)
            #pragma unroll
            for (int r = 0; r < 4; r++) of[m][d][r] = 0.f;
    float ls[2][2] = {{0.f, 0.f}, {0.f, 0.f}};

    const int ktmax = 2 * qt + 1;
    KV_ISSUE(0, 0);

    for (int kt = 0; kt <= ktmax; ++kt) {
        const int st = kt & 1;
        __syncthreads();
        if (kt < ktmax) {
            KV_ISSUE(kt + 1, st ^ 1);
            asm volatile("cp.async.wait_group 1;" ::: "memory");
        } else {
            asm volatile("cp.async.wait_group 0;" ::: "memory");
        }
        __syncthreads();

        // Fully-masked warps skip the last diagonal tile (bit-identical).
        if (kt == ktmax && warp < 2) continue;

        const unsigned* K0 = Ks + st * KSTG2;
        const unsigned* V0 = Vs + st * VSTG2;

        // ---- S = Q K^T ----
        float c[2][8][4];
        #pragma unroll
        for (int m = 0; m < 2; m++)
            #pragma unroll
            for (int nf = 0; nf < 8; nf++)
                #pragma unroll
                for (int r = 0; r < 4; r++) c[m][nf][r] = 0.f;

        #pragma unroll
        for (int ks = 0; ks < 4; ks++) {
            unsigned b0[8], b1[8];
            #pragma unroll
            for (int nf = 0; nf < 8; nf++) {
                int cidx = nf * 8 + g;
                b0[nf] = K0[(ks * 8 + tq) * KST + cidx];
                b1[nf] = K0[(ks * 8 + tq + 4) * KST + cidx];
            }
            #pragma unroll
            for (int m = 0; m < 2; m++)
                #pragma unroll
                for (int nf = 0; nf < 8; nf++)
                    mma16(c[m][nf], qf[m][ks][0], qf[m][ks][1],
                          qf[m][ks][2], qf[m][ks][3], b0[nf], b1[nf]);
        }

        // ---- causal mask ----
        if (kt >= 2 * qt) {
            const int base = kt * 64;
            #pragma unroll
            for (int m = 0; m < 2; m++) {
                int r0 = q0w + 16 * m + g, r1 = r0 + 8;
                #pragma unroll
                for (int nf = 0; nf < 8; nf++) {
                    int col = base + nf * 8 + 2 * tq;
                    if (col     > r0) c[m][nf][0] = -1e30f;
                    if (col + 1 > r0) c[m][nf][1] = -1e30f;
                    if (col     > r1) c[m][nf][2] = -1e30f;
                    if (col + 1 > r1) c[m][nf][3] = -1e30f;
                }
            }
        }

        // ---- p = exp(s/32) ----
        #pragma unroll
        for (int m = 0; m < 2; m++)
            #pragma unroll
            for (int nf = 0; nf < 8; nf++) {
                c[m][nf][0] = __expf(c[m][nf][0] * 0.03125f);
                c[m][nf][1] = __expf(c[m][nf][1] * 0.03125f);
                c[m][nf][2] = __expf(c[m][nf][2] * 0.03125f);
                c[m][nf][3] = __expf(c[m][nf][3] * 0.03125f);
                ls[m][0] += c[m][nf][0] + c[m][nf][1];
                ls[m][1] += c[m][nf][2] + c[m][nf][3];
            }

        // ---- O += P V : pack P directly into A-fragments ----
        #pragma unroll
        for (int j = 0; j < 4; j++) {
            unsigned A[2][4];
            #pragma unroll
            for (int m = 0; m < 2; m++) {
                A[m][0] = packh2(c[m][2 * j][1],     c[m][2 * j][0]);
                A[m][1] = packh2(c[m][2 * j][3],     c[m][2 * j][2]);
                A[m][2] = packh2(c[m][2 * j + 1][1], c[m][2 * j + 1][0]);
                A[m][3] = packh2(c[m][2 * j + 1][3], c[m][2 * j + 1][2]);
            }
            #pragma unroll
            for (int df = 0; df < 8; df++) {
                int cidx = df * 8 + g;
                unsigned vb0 = V0[(j * 8 + tq) * VST + cidx];
                unsigned vb1 = V0[(j * 8 + tq + 4) * VST + cidx];
                mma16(of[0][df], A[0][0], A[0][1], A[0][2], A[0][3], vb0, vb1);
                mma16(of[1][df], A[1][0], A[1][1], A[1][2], A[1][3], vb0, vb1);
            }
        }
    }
#undef KV_ISSUE

    #pragma unroll
    for (int m = 0; m < 2; m++)
        #pragma unroll
        for (int r = 0; r < 2; r++) {
            ls[m][r] += __shfl_xor_sync(FULLM, ls[m][r], 1);
            ls[m][r] += __shfl_xor_sync(FULLM, ls[m][r], 2);
        }

    // epilogue: fp16-pack g_attn (consumed by out-proj mma)
    const int bb = bh >> 4, hh = bh & 15;
    #pragma unroll
    for (int m = 0; m < 2; m++) {
        float i0 = 1.f / ls[m][0], i1 = 1.f / ls[m][1];
        int rowa = q0w + 16 * m + g, rowb = rowa + 8;
        unsigned* oa = g_attn16 + (size_t)(bb * T_ + rowa) * 512 + hh * 32;
        unsigned* ob = g_attn16 + (size_t)(bb * T_ + rowb) * 512 + hh * 32;
        #pragma unroll
        for (int df = 0; df < 8; df++) {
            oa[df * 4 + tq] = packh2(of[m][df][1] * i0, of[m][df][0] * i0);
            ob[df * 4 + tq] = packh2(of[m][df][3] * i1, of[m][df][2] * i1);
        }
    }
}

// ---------------------------------------------------------------------------
// Kernel 3: out projection via fp16 mma. DELTA vs R16: m-tile 16 (256 CTAs,
// ~2 CTAs/SM) and k-chunk 64 (16 iterations), 4-stage cp.async ring.
// Same per-element k order -> bit-identical result.
// ---------------------------------------------------------------------------
#define OAST 36
#define OBST 72
#define OASTG (16*OAST)   // 576 uints per stage
#define OBSTG (32*OBST)   // 2304 uints per stage

__global__ __launch_bounds__(128) void out_mma_kernel(
    const float* __restrict__ bo, float* __restrict__ out)
{
    __shared__ unsigned As3[4 * OASTG];
    __shared__ unsigned Bs3[4 * OBSTG];

    const int m0 = blockIdx.x * 16;
    const int tid = threadIdx.x, lane = tid & 31, warp = tid >> 5;
    const int g = lane >> 2, tq = lane & 3;
    const int wn = warp * 16;

    const unsigned sA = (unsigned)__cvta_generic_to_shared(As3);
    const unsigned sB = (unsigned)__cvta_generic_to_shared(Bs3);

#define OISSUE(CH, ST) do {                                                   \
    {                                                                         \
        int row_ = tid >> 3, c4_ = tid & 7;                                   \
        unsigned da_ = sA + (unsigned)(((ST) * OASTG + row_ * OAST + c4_ * 4) * 4); \
        asm volatile("cp.async.cg.shared.global [%0], [%1], 16;"              \
            :: "r"(da_), "l"(g_attn16 + (size_t)(m0 + row_) * 512             \
                             + (CH) * 32 + c4_ * 4));                         \
    }                                                                         \
    _Pragma("unroll")                                                         \
    for (int u_ = 0; u_ < 4; u_++) {                                          \
        int k2r_ = (tid >> 4) + 8 * u_;                                       \
        int c4_ = tid & 15;                                                   \
        unsigned db_ = sB + (unsigned)(((ST) * OBSTG + k2r_ * OBST + c4_ * 4) * 4); \
        asm volatile("cp.async.cg.shared.global [%0], [%1], 16;"              \
            :: "r"(db_), "l"(g_wo16 + (size_t)((CH) * 32 + k2r_) * 64 + c4_ * 4)); \
    }                                                                         \
    asm volatile("cp.async.commit_group;" ::: "memory");                      \
} while (0)

    float acc[2][4];
    #pragma unroll
    for (int j = 0; j < 2; j++)
        #pragma unroll
        for (int r = 0; r < 4; r++) acc[j][r] = 0.f;

    OISSUE(0, 0);
    OISSUE(1, 1);
    OISSUE(2, 2);

    for (int ch = 0; ch < 16; ++ch) {
        const int st = ch & 3;
        __syncthreads();   // all warps done with chunk ch-1 (slot (ch+3)&3)
        if (ch < 13) {
            OISSUE(ch + 3, (ch + 3) & 3);
            asm volatile("cp.async.wait_group 3;" ::: "memory");
        } else if (ch == 13) {
            asm volatile("cp.async.wait_group 2;" ::: "memory");
        } else if (ch == 14) {
            asm volatile("cp.async.wait_group 1;" ::: "memory");
        } else {
            asm volatile("cp.async.wait_group 0;" ::: "memory");
        }
        __syncthreads();

        const unsigned* A0 = As3 + st * OASTG;
        const unsigned* B0 = Bs3 + st * OBSTG;
        #pragma unroll
        for (int ks = 0; ks < 4; ++ks) {
            int r0 = g * OAST + ks * 8 + tq;
            int r1 = r0 + 8 * OAST;
            unsigned a0 = A0[r0];
            unsigned a2 = A0[r0 + 4];
            unsigned a1 = A0[r1];
            unsigned a3 = A0[r1 + 4];
            #pragma unroll
            for (int nf = 0; nf < 2; nf++) {
                int cidx = wn + nf * 8 + g;
                unsigned b0 = B0[(ks * 8 + tq) * OBST + cidx];
                unsigned b1 = B0[(ks * 8 + tq + 4) * OBST + cidx];
                mma16(acc[nf], a0, a1, a2, a3, b0, b1);
            }
        }
    }

    const int row_a = m0 + g, row_b = row_a + 8;
    #pragma unroll
    for (int nf = 0; nf < 2; nf++) {
        int col = wn + nf * 8 + 2 * tq;
        float2 bias = *(const float2*)(bo + col);
        *(float2*)(out + (size_t)row_a * DOUT_ + col)
            = make_float2(acc[nf][0] + bias.x, acc[nf][1] + bias.y);
        *(float2*)(out + (size_t)row_b * DOUT_ + col)
            = make_float2(acc[nf][2] + bias.x, acc[nf][3] + bias.y);
    }
#undef OISSUE
}

// ---------------------------------------------------------------------------
extern "C" void kernel_launch(void* const* d_in, const int* in_sizes, int n_in,
                              void* d_out, int out_size)
{
    const float* x  = (const float*)d_in[0];
    const float* Wq = (const float*)d_in[1];
    const float* Wk = (const float*)d_in[2];
    const float* Wv = (const float*)d_in[3];
    const float* Wo = (const float*)d_in[4];
    const float* bo = (const float*)d_in[5];
    float* out = (float*)d_out;
    (void)in_sizes; (void)n_in; (void)out_size;

    pack16_all<<<(PRETOT + 255) / 256, 256>>>(
        (const float4*)x, Wq, Wk, Wv, Wo);

    qkv_mma_kernel<<<dim3(8, 32, 3), 128>>>();
    attn_mma_kernel<<<512, 128>>>();
    out_mma_kernel<<<BT_ / 16, 128>>>(bo, out);
}